// round 6
// baseline (speedup 1.0000x reference)
#include <cuda_runtime.h>
#include <cuda_fp16.h>
#include <cstdint>

#define NTHR 256
#define TOKB 128
#define EXPN 64
#define CDIM 2048
#define BT   16384
#define BDIM 4
#define TOPK 6
#define KSTEP_U32 512            // u32 per kstep of packed W (4 jp * 32 lanes * 4)
#define CHUNK_U32 (4*KSTEP_U32)  // 2048 u32 = 8 KB (4 ksteps)
#define LSTR 66
#define TAU  1.4e-3f
#define SMEM_BYTES (4*CHUNK_U32*4 + TOKB*LSTR*4)   // 32768 + 33792 = 66560

__device__ float g_sums[BDIM * EXPN];
__device__ float g_cnts[BDIM * EXPN];
__device__ int   g_npair, g_nfull;
__device__ int   g_ptok[BT];
__device__ int   g_pinfo[BT];
__device__ float2 g_pw[BT];
__device__ int   g_ffull[BT];
__device__ uint32_t wsg[128 * KSTEP_U32];   // 256 KB packed fp16 W fragments

static __device__ __forceinline__ void cp16(void* smem_ptr, const void* gptr) {
    unsigned saddr = (unsigned)__cvta_generic_to_shared(smem_ptr);
    asm volatile("cp.async.cg.shared.global [%0], [%1], 16;\n" :: "r"(saddr), "l"(gptr));
}
#define CP_COMMIT() asm volatile("cp.async.commit_group;\n" ::: "memory")

static __device__ __forceinline__ void mma16816(float* c, const uint32_t* a,
                                                uint32_t b0, uint32_t b1) {
    asm volatile("mma.sync.aligned.m16n8k16.row.col.f32.f16.f16.f32 "
        "{%0,%1,%2,%3}, {%4,%5,%6,%7}, {%8,%9}, {%0,%1,%2,%3};"
        : "+f"(c[0]), "+f"(c[1]), "+f"(c[2]), "+f"(c[3])
        : "r"(a[0]), "r"(a[1]), "r"(a[2]), "r"(a[3]), "r"(b0), "r"(b1));
}

// exact 2-way fp16 split of a float pair -> two half2 words (lo=f0, hi=f1)
static __device__ __forceinline__ void split2h(float f0, float f1,
                                               uint32_t& o0, uint32_t& o1) {
    __half2 h = __floats2half2_rn(f0, f1);
    o0 = *(uint32_t*)&h;
    float2 g = __half22float2(h);
    __half2 r = __floats2half2_rn(f0 - g.x, f1 - g.y);
    o1 = *(uint32_t*)&r;
}

// ---------------- W prep: single fp16 plane, packed in B-fragment lane order ----------------
__global__ void prep_kernel(const float* __restrict__ w) {
    int id = blockIdx.x * 256 + threadIdx.x;   // 32768 = 128 ksteps * 8 ntiles * 32 lanes
    if (id < BDIM * EXPN) { g_sums[id] = 0.f; g_cnts[id] = 0.f; }
    if (id == 0) { g_npair = 0; g_nfull = 0; }
    int s = id >> 8;
    int j = (id >> 5) & 7;
    int l = id & 31;
    int n  = 8 * j + (l >> 2);
    int k0 = s * 16 + (l & 3) * 2;
    const float* wr = w + (size_t)n * CDIM + k0;
    float2 flo = *(const float2*)wr;
    float2 fhi = *(const float2*)(wr + 8);
    __half2 b0 = __floats2half2_rn(flo.x, flo.y);
    __half2 b1 = __floats2half2_rn(fhi.x, fhi.y);
    uint32_t base = (uint32_t)(((s * 4 + (j >> 1)) * 32 + l) * 4 + (j & 1) * 2);
    wsg[base]     = *(uint32_t*)&b0;
    wsg[base + 1] = *(uint32_t*)&b1;
}

// ---------------- main gate kernel ----------------
__global__ void __launch_bounds__(NTHR, 1)
gate_kernel(const float* __restrict__ x, float* __restrict__ out) {
    extern __shared__ char smem[];
    uint32_t* wbuf = (uint32_t*)smem;                 // 4 x 8KB chunk buffers
    float* lsm = (float*)(smem + 4 * CHUNK_U32 * 4);  // 128 x 66 logits
    __shared__ float s_sums[EXPN];
    __shared__ float s_cnt[EXPN];

    const int tid  = threadIdx.x;
    const int wid  = tid >> 5;
    const int lane = tid & 31;
    const int blk  = blockIdx.x;
    const int wg   = wid & 3;    // token group (32 tokens)
    const int kh   = wid >> 2;   // k-half

    if (tid < EXPN) { s_sums[tid] = 0.f; s_cnt[tid] = 0.f; }

    const int r  = lane >> 2;
    const int c0 = (lane & 3) * 2;
    const float* xr0 = x + ((size_t)blk * TOKB + wg * 32 + r) * CDIM + kh * 1024;
    const float* xr1 = xr0 + (size_t)16 * CDIM;

    float cacc[2][8][4];
#pragma unroll
    for (int m = 0; m < 2; m++)
#pragma unroll
        for (int j = 0; j < 8; j++)
#pragma unroll
            for (int q = 0; q < 4; q++) cacc[m][j][q] = 0.f;

    auto load2 = [&](int c) {
        int par = c & 1;
        const uint4* s0 = (const uint4*)(wsg + (size_t)c * CHUNK_U32);
        const uint4* s1 = (const uint4*)(wsg + (size_t)(16 + c) * CHUNK_U32);
        uint4* d0 = (uint4*)(wbuf + par * CHUNK_U32);
        uint4* d1 = (uint4*)(wbuf + (2 + par) * CHUNK_U32);
#pragma unroll
        for (int i = 0; i < 2; i++) cp16(d0 + tid + i * NTHR, s0 + tid + i * NTHR);
#pragma unroll
        for (int i = 0; i < 2; i++) cp16(d1 + tid + i * NTHR, s1 + tid + i * NTHR);
        CP_COMMIT();
    };

    float2 xf[2][8];
    auto ldx = [&](float2* d, int ks) {
        const float* p0 = xr0 + ks * 16 + c0;
        const float* p1 = xr1 + ks * 16 + c0;
        d[0] = *(const float2*)p0;
        d[1] = *(const float2*)(p0 + 8 * CDIM);
        d[2] = *(const float2*)(p0 + 8);
        d[3] = *(const float2*)(p0 + 8 * CDIM + 8);
        d[4] = *(const float2*)p1;
        d[5] = *(const float2*)(p1 + 8 * CDIM);
        d[6] = *(const float2*)(p1 + 8);
        d[7] = *(const float2*)(p1 + 8 * CDIM + 8);
    };

    load2(0);
    load2(1);
    ldx(xf[0], 0);

    for (int c = 0; c < 16; c++) {
        if (c + 1 < 16) asm volatile("cp.async.wait_group 1;\n" ::: "memory");
        else            asm volatile("cp.async.wait_group 0;\n" ::: "memory");
        __syncthreads();

        const uint32_t* wb = wbuf + (kh * 2 + (c & 1)) * CHUNK_U32;

#pragma unroll
        for (int kc = 0; kc < 4; kc++) {
            const int ks = c * 4 + kc;
            const float2* xc = xf[kc & 1];
            if (ks + 1 < 64) ldx(xf[(kc & 1) ^ 1], ks + 1);

            uint32_t A0[2][4], A1[2][4];
#pragma unroll
            for (int m = 0; m < 2; m++)
#pragma unroll
                for (int q = 0; q < 4; q++)
                    split2h(xc[m * 4 + q].x, xc[m * 4 + q].y, A0[m][q], A1[m][q]);

            const uint4* wk = (const uint4*)(wb + kc * KSTEP_U32) + lane;
#pragma unroll
            for (int jp = 0; jp < 4; jp++) {
                uint4 G = wk[jp * 32];
                float* c00 = cacc[0][2 * jp];
                float* c01 = cacc[0][2 * jp + 1];
                float* c10 = cacc[1][2 * jp];
                float* c11 = cacc[1][2 * jp + 1];
                mma16816(c00, A0[0], G.x, G.y);
                mma16816(c01, A0[0], G.z, G.w);
                mma16816(c10, A0[1], G.x, G.y);
                mma16816(c11, A0[1], G.z, G.w);
                mma16816(c00, A1[0], G.x, G.y);
                mma16816(c01, A1[0], G.z, G.w);
                mma16816(c10, A1[1], G.x, G.y);
                mma16816(c11, A1[1], G.z, G.w);
            }
        }
        __syncthreads();
        if (c + 2 < 16) load2(c + 2);
    }

    // ---- combine k-halves ----
    if (kh == 0) {
#pragma unroll
        for (int m = 0; m < 2; m++)
#pragma unroll
            for (int j = 0; j < 8; j++) {
                int row = wg * 32 + m * 16 + r;
                int nb = 8 * j + c0;
                *(float2*)&lsm[row * LSTR + nb]       = make_float2(cacc[m][j][0], cacc[m][j][1]);
                *(float2*)&lsm[(row + 8) * LSTR + nb] = make_float2(cacc[m][j][2], cacc[m][j][3]);
            }
    }
    __syncthreads();
    if (kh == 1) {
#pragma unroll
        for (int m = 0; m < 2; m++)
#pragma unroll
            for (int j = 0; j < 8; j++) {
                int row = wg * 32 + m * 16 + r;
                int nb = 8 * j + c0;
                float2 a = *(float2*)&lsm[row * LSTR + nb];
                float2 b = *(float2*)&lsm[(row + 8) * LSTR + nb];
                *(float2*)&lsm[row * LSTR + nb]       = make_float2(a.x + cacc[m][j][0], a.y + cacc[m][j][1]);
                *(float2*)&lsm[(row + 8) * LSTR + nb] = make_float2(b.x + cacc[m][j][2], b.y + cacc[m][j][3]);
            }
    }
    __syncthreads();

    // ---- per-token epilogue: top-8 tracking + pair/full flagging ----
    if (tid < TOKB) {
        float* row = lsm + tid * LSTR;

        float v0=-1e38f,v1=-1e38f,v2=-1e38f,v3=-1e38f,v4=-1e38f,v5=-1e38f,v6=-1e38f,v7=-1e38f;
        int   i0=0,i1=0,i2=0,i3=0,i4=0,i5=0,i6=0;
        for (int e = 0; e < EXPN; e++) {
            float l = row[e];
            if (l > v7) {
                v7 = l;
                int ie = e;
                if (v7 > v6) { float t=v6; v6=v7; v7=t; int u=i6; i6=ie; ie=u;
                if (v6 > v5) { t=v5; v5=v6; v6=t; u=i5; i5=i6; i6=u;
                if (v5 > v4) { t=v4; v4=v5; v5=t; u=i4; i4=i5; i5=u;
                if (v4 > v3) { t=v3; v3=v4; v4=t; u=i3; i3=i4; i4=u;
                if (v3 > v2) { t=v2; v2=v3; v3=t; u=i2; i2=i3; i3=u;
                if (v2 > v1) { t=v1; v1=v2; v2=t; u=i1; i1=i2; i2=u;
                if (v1 > v0) { t=v0; v0=v1; v1=t; u=i0; i0=i1; i1=u; } } } } } } }
            }
        }

        float m = v0;
        float ssum = 0.f;
        for (int e = 0; e < EXPN; e++) {
            float p = expf(row[e] - m);
            ssum += p;
            row[e] = p;
        }
        float inv = 1.0f / ssum;
        const int tok = blk * TOKB + tid;

        // flagging
        int cnt = 0, a = 0;
        if (v0 - v1 < TAU) { cnt++; a = 0; }
        if (v1 - v2 < TAU) { cnt++; a = 1; }
        if (v2 - v3 < TAU) { cnt++; a = 2; }
        if (v3 - v4 < TAU) { cnt++; a = 3; }
        if (v4 - v5 < TAU) { cnt++; a = 4; }
        if (v5 - v6 < TAU) { cnt++; a = 5; }
        if (cnt > 0) {
            bool full = (cnt >= 2) || (a == 5 && (v6 - v7 < TAU));
            if (full) {
                int slot = atomicAdd(&g_nfull, 1);
                g_ffull[slot] = tok;
            } else {
                int ia = a==0?i0 : a==1?i1 : a==2?i2 : a==3?i3 : a==4?i4 : i5;
                int ib = a==0?i1 : a==1?i2 : a==2?i3 : a==3?i4 : a==4?i5 : i6;
                int slot = atomicAdd(&g_npair, 1);
                g_ptok[slot] = tok;
                g_pinfo[slot] = a | (ia << 3) | (ib << 9);
                g_pw[slot] = make_float2(row[ia] * inv, row[ib] * inv);
            }
        }

        const size_t g = (size_t)tok;
        float* out_idx = out;
        float* out_wgt = out + (size_t)BT * TOPK;

        out_idx[g * TOPK + 0] = (float)i0;
        out_idx[g * TOPK + 1] = (float)i1;
        out_idx[g * TOPK + 2] = (float)i2;
        out_idx[g * TOPK + 3] = (float)i3;
        out_idx[g * TOPK + 4] = (float)i4;
        out_idx[g * TOPK + 5] = (float)i5;

        out_wgt[g * TOPK + 0] = row[i0] * inv;
        out_wgt[g * TOPK + 1] = row[i1] * inv;
        out_wgt[g * TOPK + 2] = row[i2] * inv;
        out_wgt[g * TOPK + 3] = row[i3] * inv;
        out_wgt[g * TOPK + 4] = row[i4] * inv;
        out_wgt[g * TOPK + 5] = row[i5] * inv;

        for (int jj = 0; jj < EXPN; jj++) {
            int e = (tid + jj) & (EXPN - 1);
            atomicAdd(&s_sums[e], row[e] * inv);
        }
        atomicAdd(&s_cnt[i0], 1.0f);
        atomicAdd(&s_cnt[i1], 1.0f);
        atomicAdd(&s_cnt[i2], 1.0f);
        atomicAdd(&s_cnt[i3], 1.0f);
        atomicAdd(&s_cnt[i4], 1.0f);
        atomicAdd(&s_cnt[i5], 1.0f);
    }
    __syncthreads();

    if (tid < EXPN) {
        int b = blk >> 5;
        atomicAdd(&g_sums[b * EXPN + tid], s_sums[tid]);
        atomicAdd(&g_cnts[b * EXPN + tid], s_cnt[tid]);
    }
}

// ---------------- fix kernel: pair swaps + full recompute + aux ----------------
// exact logits replicate R1 fp32 order: even-k fmaf chain + odd-k fmaf chain, then add.
__global__ void __launch_bounds__(256, 1)
fix_kernel(const float* __restrict__ x, const float* __restrict__ w,
           float* __restrict__ out) {
    __shared__ float ws[EXPN * 129];
    __shared__ float lg[4][EXPN];
    __shared__ float red[256];

    const int tid = threadIdx.x;
    float* out_idx = out;
    float* out_wgt = out + (size_t)BT * TOPK;

    // ---- Part A: pairwise exact compare for single-gap flags ----
    const int npair = g_npair;
    if (npair > 0) {
        const int lanepair = (tid & 31) >> 1;
        const int warpbase = (blockIdx.x * 256 + (tid & ~31)) >> 1;
        const int stride = (gridDim.x * 256) >> 1;
        for (int pb = warpbase; pb < npair; pb += stride) {
            int p = pb + lanepair;
            bool act = (p < npair);
            int pp = act ? p : (npair - 1);
            int tok = g_ptok[pp];
            int info = g_pinfo[pp];
            int a = info & 7, ia = (info >> 3) & 63, ib = (info >> 9) & 63;
            int e = (tid & 1) ? ib : ia;
            const float4* xp = (const float4*)(x + (size_t)tok * CDIM);
            const float4* wp = (const float4*)(w + (size_t)e * CDIM);
            float accE = 0.f, accO = 0.f;
#pragma unroll 8
            for (int i = 0; i < 512; i++) {
                float4 xv = xp[i];
                float4 wv = wp[i];
                accE = fmaf(xv.x, wv.x, accE);
                accO = fmaf(xv.y, wv.y, accO);
                accE = fmaf(xv.z, wv.z, accE);
                accO = fmaf(xv.w, wv.w, accO);
            }
            float L = accE + accO;
            float Lo = __shfl_xor_sync(0xFFFFFFFF, L, 1);
            if (act && !(tid & 1)) {
                bool sw = (Lo > L);   // exact order: ib before ia?
                float2 pw = g_pw[pp];
                float fi = (float)(sw ? ib : ia), si = (float)(sw ? ia : ib);
                float fp = sw ? pw.y : pw.x,      sp = sw ? pw.x : pw.y;
                out_idx[(size_t)tok * TOPK + a] = fi;
                out_wgt[(size_t)tok * TOPK + a] = fp;
                if (a < 5) {
                    out_idx[(size_t)tok * TOPK + a + 1] = si;
                    out_wgt[(size_t)tok * TOPK + a + 1] = sp;
                }
            }
        }
    }
    __syncthreads();

    // ---- Part B: full 64-expert exact recompute (rare) ----
    const int nfull = g_nfull;
    const int tg = tid >> 6;
    const int e  = tid & 63;
    for (int base = blockIdx.x * 4; base < nfull; base += gridDim.x * 4) {
        const int fi = base + tg;
        const int tok = g_ffull[fi < nfull ? fi : (nfull - 1)];

        float accE = 0.f, accO = 0.f;
        for (int ch = 0; ch < 16; ch++) {
            __syncthreads();
            for (int i = tid; i < EXPN * 32; i += 256) {
                int row = i >> 5;
                int c4  = i & 31;
                float4 v = *(const float4*)(w + (size_t)row * CDIM + ch * 128 + c4 * 4);
                float* d = &ws[row * 129 + c4 * 4];
                d[0] = v.x; d[1] = v.y; d[2] = v.z; d[3] = v.w;
            }
            __syncthreads();
            const float* xp = x + (size_t)tok * CDIM + ch * 128;
            const float* wr = &ws[e * 129];
#pragma unroll 8
            for (int kk = 0; kk < 128; kk += 2) {
                float2 xv = *(const float2*)(xp + kk);
                accE = fmaf(xv.x, wr[kk],     accE);
                accO = fmaf(xv.y, wr[kk + 1], accO);
            }
        }
        lg[tg][e] = accE + accO;
        __syncthreads();

        if (tid < 4 && base + tid < nfull) {
            const int t2 = g_ffull[base + tid];
            const float* row = lg[tid];
            float v0=-1e38f,v1=-1e38f,v2=-1e38f,v3=-1e38f,v4=-1e38f,v5=-1e38f;
            int   i0=0,i1=0,i2=0,i3=0,i4=0,i5=0;
            for (int k = 0; k < EXPN; k++) {
                float l = row[k];
                if (l > v5) {
                    v5 = l; i5 = k;
                    if (v5 > v4) { float t=v4; v4=v5; v5=t; int u=i4; i4=i5; i5=u; }
                    if (v4 > v3) { float t=v3; v3=v4; v4=t; int u=i3; i3=i4; i4=u; }
                    if (v3 > v2) { float t=v2; v2=v3; v3=t; int u=i2; i2=i3; i3=u; }
                    if (v2 > v1) { float t=v1; v1=v2; v2=t; int u=i1; i1=i2; i2=u; }
                    if (v1 > v0) { float t=v0; v0=v1; v1=t; int u=i0; i0=i1; i1=u; }
                }
            }
            float m = v0;
            float ssum = 0.f;
            for (int k = 0; k < EXPN; k++) ssum += expf(row[k] - m);
            float inv = 1.0f / ssum;
            const size_t g = (size_t)t2;
            out_idx[g * TOPK + 0] = (float)i0;
            out_idx[g * TOPK + 1] = (float)i1;
            out_idx[g * TOPK + 2] = (float)i2;
            out_idx[g * TOPK + 3] = (float)i3;
            out_idx[g * TOPK + 4] = (float)i4;
            out_idx[g * TOPK + 5] = (float)i5;
            out_wgt[g * TOPK + 0] = expf(v0 - m) * inv;
            out_wgt[g * TOPK + 1] = expf(v1 - m) * inv;
            out_wgt[g * TOPK + 2] = expf(v2 - m) * inv;
            out_wgt[g * TOPK + 3] = expf(v3 - m) * inv;
            out_wgt[g * TOPK + 4] = expf(v4 - m) * inv;
            out_wgt[g * TOPK + 5] = expf(v5 - m) * inv;
        }
        __syncthreads();
    }

    // ---- Part C: aux loss (block 0) ----
    if (blockIdx.x == 0) {
        red[tid] = g_cnts[tid] * g_sums[tid];
        __syncthreads();
#pragma unroll
        for (int s = 128; s > 0; s >>= 1) {
            if (tid < s) red[tid] += red[tid + s];
            __syncthreads();
        }
        if (tid == 0) {
            const float scale = (float)(0.001 * 64.0 / ((double)4 * 4096.0 * 6.0 * 4096.0));
            out[(size_t)BT * 12] = red[0] * scale;
        }
    }
}

extern "C" void kernel_launch(void* const* d_in, const int* in_sizes, int n_in,
                              void* d_out, int out_size) {
    const float* x = (const float*)d_in[0];
    const float* w = (const float*)d_in[1];
    float* out = (float*)d_out;

    cudaFuncSetAttribute(gate_kernel, cudaFuncAttributeMaxDynamicSharedMemorySize, SMEM_BYTES);

    prep_kernel<<<128, 256>>>(w);
    gate_kernel<<<BT / TOKB, NTHR, SMEM_BYTES>>>(x, out);
    fix_kernel<<<128, 256>>>(x, w, out);
}

// round 7
// speedup vs baseline: 1.0031x; 1.0031x over previous
#include <cuda_runtime.h>
#include <cuda_fp16.h>
#include <cstdint>

#define NTHR 256
#define TOKB 128
#define EXPN 64
#define CDIM 2048
#define BT   16384
#define BDIM 4
#define TOPK 6
#define KSTEP_U32 512            // u32 per kstep of packed W (4 jp * 32 lanes * 4)
#define CHUNK_U32 (4*KSTEP_U32)  // 2048 u32 = 8 KB (4 ksteps)
#define LSTR 66
#define TAU  1.4e-3f
#define SMEM_BYTES (4*CHUNK_U32*4 + TOKB*LSTR*4)   // 32768 + 33792 = 66560
#define FIX_SMEM ((128*129 + 64*129 + 256)*4)      // 100096

__device__ float g_sums[BDIM * EXPN];
__device__ float g_cnts[BDIM * EXPN];
__device__ int   g_npair, g_nfull;
__device__ int   g_ptok[BT];
__device__ int   g_pinfo[BT];
__device__ float2 g_pw[BT];
__device__ int   g_ffull[BT];
__device__ uint32_t wsg[128 * KSTEP_U32];   // 256 KB packed fp16 W fragments

static __device__ __forceinline__ void cp16(void* smem_ptr, const void* gptr) {
    unsigned saddr = (unsigned)__cvta_generic_to_shared(smem_ptr);
    asm volatile("cp.async.cg.shared.global [%0], [%1], 16;\n" :: "r"(saddr), "l"(gptr));
}
#define CP_COMMIT() asm volatile("cp.async.commit_group;\n" ::: "memory")

static __device__ __forceinline__ void mma16816(float* c, const uint32_t* a,
                                                uint32_t b0, uint32_t b1) {
    asm volatile("mma.sync.aligned.m16n8k16.row.col.f32.f16.f16.f32 "
        "{%0,%1,%2,%3}, {%4,%5,%6,%7}, {%8,%9}, {%0,%1,%2,%3};"
        : "+f"(c[0]), "+f"(c[1]), "+f"(c[2]), "+f"(c[3])
        : "r"(a[0]), "r"(a[1]), "r"(a[2]), "r"(a[3]), "r"(b0), "r"(b1));
}

// exact 2-way fp16 split of a float pair
static __device__ __forceinline__ void split2h(float f0, float f1,
                                               uint32_t& o0, uint32_t& o1) {
    __half2 h = __floats2half2_rn(f0, f1);
    o0 = *(uint32_t*)&h;
    float2 g = __half22float2(h);
    __half2 r = __floats2half2_rn(f0 - g.x, f1 - g.y);
    o1 = *(uint32_t*)&r;
}

// ---------------- W prep: single fp16 plane, packed in B-fragment lane order ----------------
__global__ void prep_kernel(const float* __restrict__ w) {
    int id = blockIdx.x * 256 + threadIdx.x;   // 32768 = 128 ksteps * 8 ntiles * 32 lanes
    if (id < BDIM * EXPN) { g_sums[id] = 0.f; g_cnts[id] = 0.f; }
    if (id == 0) { g_npair = 0; g_nfull = 0; }
    int s = id >> 8;
    int j = (id >> 5) & 7;
    int l = id & 31;
    int n  = 8 * j + (l >> 2);
    int k0 = s * 16 + (l & 3) * 2;
    const float* wr = w + (size_t)n * CDIM + k0;
    float2 flo = *(const float2*)wr;
    float2 fhi = *(const float2*)(wr + 8);
    __half2 b0 = __floats2half2_rn(flo.x, flo.y);
    __half2 b1 = __floats2half2_rn(fhi.x, fhi.y);
    uint32_t base = (uint32_t)(((s * 4 + (j >> 1)) * 32 + l) * 4 + (j & 1) * 2);
    wsg[base]     = *(uint32_t*)&b0;
    wsg[base + 1] = *(uint32_t*)&b1;
}

// ---------------- main gate kernel ----------------
__global__ void __launch_bounds__(NTHR, 1)
gate_kernel(const float* __restrict__ x, float* __restrict__ out) {
    extern __shared__ char smem[];
    uint32_t* wbuf = (uint32_t*)smem;                 // 4 x 8KB chunk buffers
    float* lsm = (float*)(smem + 4 * CHUNK_U32 * 4);  // 128 x 66 logits
    __shared__ float s_sums[EXPN];
    __shared__ float s_cnt[EXPN];

    const int tid  = threadIdx.x;
    const int wid  = tid >> 5;
    const int lane = tid & 31;
    const int blk  = blockIdx.x;
    const int wg   = wid & 3;    // token group (32 tokens)
    const int kh   = wid >> 2;   // k-half

    if (tid < EXPN) { s_sums[tid] = 0.f; s_cnt[tid] = 0.f; }

    const int r  = lane >> 2;
    const int c0 = (lane & 3) * 2;
    const float* xr0 = x + ((size_t)blk * TOKB + wg * 32 + r) * CDIM + kh * 1024;
    const float* xr1 = xr0 + (size_t)16 * CDIM;

    float cacc[2][8][4];
#pragma unroll
    for (int m = 0; m < 2; m++)
#pragma unroll
        for (int j = 0; j < 8; j++)
#pragma unroll
            for (int q = 0; q < 4; q++) cacc[m][j][q] = 0.f;

    auto load2 = [&](int c) {
        int par = c & 1;
        const uint4* s0 = (const uint4*)(wsg + (size_t)c * CHUNK_U32);
        const uint4* s1 = (const uint4*)(wsg + (size_t)(16 + c) * CHUNK_U32);
        uint4* d0 = (uint4*)(wbuf + par * CHUNK_U32);
        uint4* d1 = (uint4*)(wbuf + (2 + par) * CHUNK_U32);
#pragma unroll
        for (int i = 0; i < 2; i++) cp16(d0 + tid + i * NTHR, s0 + tid + i * NTHR);
#pragma unroll
        for (int i = 0; i < 2; i++) cp16(d1 + tid + i * NTHR, s1 + tid + i * NTHR);
        CP_COMMIT();
    };

    load2(0);
    load2(1);

    for (int c = 0; c < 16; c++) {
        if (c + 1 < 16) asm volatile("cp.async.wait_group 1;\n" ::: "memory");
        else            asm volatile("cp.async.wait_group 0;\n" ::: "memory");
        __syncthreads();

        const uint32_t* wb = wbuf + (kh * 2 + (c & 1)) * CHUNK_U32;

#pragma unroll
        for (int kc = 0; kc < 4; kc++) {
            const int koff = (c * 4 + kc) * 16 + c0;

            uint32_t A0[2][4], A1[2][4];
#pragma unroll
            for (int m = 0; m < 2; m++) {
                const float* xp = (m == 0 ? xr0 : xr1) + koff;
                float2 l0 = *(const float2*)xp;
                float2 l1 = *(const float2*)(xp + 8 * CDIM);
                float2 h0 = *(const float2*)(xp + 8);
                float2 h1 = *(const float2*)(xp + 8 * CDIM + 8);
                split2h(l0.x, l0.y, A0[m][0], A1[m][0]);
                split2h(l1.x, l1.y, A0[m][1], A1[m][1]);
                split2h(h0.x, h0.y, A0[m][2], A1[m][2]);
                split2h(h1.x, h1.y, A0[m][3], A1[m][3]);
            }

            const uint4* wk = (const uint4*)(wb + kc * KSTEP_U32) + lane;
            uint4 G0 = wk[0];
            uint4 G1 = wk[32];
            uint4 G2 = wk[64];
            uint4 G3 = wk[96];

            // term 0 (A0): 16 MMAs, 16 distinct accumulators
            mma16816(cacc[0][0], A0[0], G0.x, G0.y);
            mma16816(cacc[0][1], A0[0], G0.z, G0.w);
            mma16816(cacc[1][0], A0[1], G0.x, G0.y);
            mma16816(cacc[1][1], A0[1], G0.z, G0.w);
            mma16816(cacc[0][2], A0[0], G1.x, G1.y);
            mma16816(cacc[0][3], A0[0], G1.z, G1.w);
            mma16816(cacc[1][2], A0[1], G1.x, G1.y);
            mma16816(cacc[1][3], A0[1], G1.z, G1.w);
            mma16816(cacc[0][4], A0[0], G2.x, G2.y);
            mma16816(cacc[0][5], A0[0], G2.z, G2.w);
            mma16816(cacc[1][4], A0[1], G2.x, G2.y);
            mma16816(cacc[1][5], A0[1], G2.z, G2.w);
            mma16816(cacc[0][6], A0[0], G3.x, G3.y);
            mma16816(cacc[0][7], A0[0], G3.z, G3.w);
            mma16816(cacc[1][6], A0[1], G3.x, G3.y);
            mma16816(cacc[1][7], A0[1], G3.z, G3.w);
            // term 1 (A1)
            mma16816(cacc[0][0], A1[0], G0.x, G0.y);
            mma16816(cacc[0][1], A1[0], G0.z, G0.w);
            mma16816(cacc[1][0], A1[1], G0.x, G0.y);
            mma16816(cacc[1][1], A1[1], G0.z, G0.w);
            mma16816(cacc[0][2], A1[0], G1.x, G1.y);
            mma16816(cacc[0][3], A1[0], G1.z, G1.w);
            mma16816(cacc[1][2], A1[1], G1.x, G1.y);
            mma16816(cacc[1][3], A1[1], G1.z, G1.w);
            mma16816(cacc[0][4], A1[0], G2.x, G2.y);
            mma16816(cacc[0][5], A1[0], G2.z, G2.w);
            mma16816(cacc[1][4], A1[1], G2.x, G2.y);
            mma16816(cacc[1][5], A1[1], G2.z, G2.w);
            mma16816(cacc[0][6], A1[0], G3.x, G3.y);
            mma16816(cacc[0][7], A1[0], G3.z, G3.w);
            mma16816(cacc[1][6], A1[1], G3.x, G3.y);
            mma16816(cacc[1][7], A1[1], G3.z, G3.w);
        }
        __syncthreads();
        if (c + 2 < 16) load2(c + 2);
    }

    // ---- combine k-halves ----
    if (kh == 0) {
#pragma unroll
        for (int m = 0; m < 2; m++)
#pragma unroll
            for (int j = 0; j < 8; j++) {
                int row = wg * 32 + m * 16 + r;
                int nb = 8 * j + c0;
                *(float2*)&lsm[row * LSTR + nb]       = make_float2(cacc[m][j][0], cacc[m][j][1]);
                *(float2*)&lsm[(row + 8) * LSTR + nb] = make_float2(cacc[m][j][2], cacc[m][j][3]);
            }
    }
    __syncthreads();
    if (kh == 1) {
#pragma unroll
        for (int m = 0; m < 2; m++)
#pragma unroll
            for (int j = 0; j < 8; j++) {
                int row = wg * 32 + m * 16 + r;
                int nb = 8 * j + c0;
                float2 a = *(float2*)&lsm[row * LSTR + nb];
                float2 b = *(float2*)&lsm[(row + 8) * LSTR + nb];
                *(float2*)&lsm[row * LSTR + nb]       = make_float2(a.x + cacc[m][j][0], a.y + cacc[m][j][1]);
                *(float2*)&lsm[(row + 8) * LSTR + nb] = make_float2(b.x + cacc[m][j][2], b.y + cacc[m][j][3]);
            }
    }
    __syncthreads();

    // ---- per-token epilogue: top-8 tracking + pair/full flagging ----
    if (tid < TOKB) {
        float* row = lsm + tid * LSTR;

        float v0=-1e38f,v1=-1e38f,v2=-1e38f,v3=-1e38f,v4=-1e38f,v5=-1e38f,v6=-1e38f,v7=-1e38f;
        int   i0=0,i1=0,i2=0,i3=0,i4=0,i5=0,i6=0;
        for (int e = 0; e < EXPN; e++) {
            float l = row[e];
            if (l > v7) {
                v7 = l;
                int ie = e;
                if (v7 > v6) { float t=v6; v6=v7; v7=t; int u=i6; i6=ie; ie=u;
                if (v6 > v5) { t=v5; v5=v6; v6=t; u=i5; i5=i6; i6=u;
                if (v5 > v4) { t=v4; v4=v5; v5=t; u=i4; i4=i5; i5=u;
                if (v4 > v3) { t=v3; v3=v4; v4=t; u=i3; i3=i4; i4=u;
                if (v3 > v2) { t=v2; v2=v3; v3=t; u=i2; i2=i3; i3=u;
                if (v2 > v1) { t=v1; v1=v2; v2=t; u=i1; i1=i2; i2=u;
                if (v1 > v0) { t=v0; v0=v1; v1=t; u=i0; i0=i1; i1=u; } } } } } } }
            }
        }

        float m = v0;
        float ssum = 0.f;
        for (int e = 0; e < EXPN; e++) {
            float p = expf(row[e] - m);
            ssum += p;
            row[e] = p;
        }
        float inv = 1.0f / ssum;
        const int tok = blk * TOKB + tid;

        int cnt = 0, a = 0;
        if (v0 - v1 < TAU) { cnt++; a = 0; }
        if (v1 - v2 < TAU) { cnt++; a = 1; }
        if (v2 - v3 < TAU) { cnt++; a = 2; }
        if (v3 - v4 < TAU) { cnt++; a = 3; }
        if (v4 - v5 < TAU) { cnt++; a = 4; }
        if (v5 - v6 < TAU) { cnt++; a = 5; }
        if (cnt > 0) {
            bool full = (cnt >= 2) || (a == 5 && (v6 - v7 < TAU));
            if (full) {
                int slot = atomicAdd(&g_nfull, 1);
                g_ffull[slot] = tok;
            } else {
                int ia = a==0?i0 : a==1?i1 : a==2?i2 : a==3?i3 : a==4?i4 : i5;
                int ib = a==0?i1 : a==1?i2 : a==2?i3 : a==3?i4 : a==4?i5 : i6;
                int slot = atomicAdd(&g_npair, 1);
                g_ptok[slot] = tok;
                g_pinfo[slot] = a | (ia << 3) | (ib << 9);
                g_pw[slot] = make_float2(row[ia] * inv, row[ib] * inv);
            }
        }

        const size_t g = (size_t)tok;
        float* out_idx = out;
        float* out_wgt = out + (size_t)BT * TOPK;

        out_idx[g * TOPK + 0] = (float)i0;
        out_idx[g * TOPK + 1] = (float)i1;
        out_idx[g * TOPK + 2] = (float)i2;
        out_idx[g * TOPK + 3] = (float)i3;
        out_idx[g * TOPK + 4] = (float)i4;
        out_idx[g * TOPK + 5] = (float)i5;

        out_wgt[g * TOPK + 0] = row[i0] * inv;
        out_wgt[g * TOPK + 1] = row[i1] * inv;
        out_wgt[g * TOPK + 2] = row[i2] * inv;
        out_wgt[g * TOPK + 3] = row[i3] * inv;
        out_wgt[g * TOPK + 4] = row[i4] * inv;
        out_wgt[g * TOPK + 5] = row[i5] * inv;

        for (int jj = 0; jj < EXPN; jj++) {
            int e = (tid + jj) & (EXPN - 1);
            atomicAdd(&s_sums[e], row[e] * inv);
        }
        atomicAdd(&s_cnt[i0], 1.0f);
        atomicAdd(&s_cnt[i1], 1.0f);
        atomicAdd(&s_cnt[i2], 1.0f);
        atomicAdd(&s_cnt[i3], 1.0f);
        atomicAdd(&s_cnt[i4], 1.0f);
        atomicAdd(&s_cnt[i5], 1.0f);
    }
    __syncthreads();

    if (tid < EXPN) {
        int b = blk >> 5;
        atomicAdd(&g_sums[b * EXPN + tid], s_sums[tid]);
        atomicAdd(&g_cnts[b * EXPN + tid], s_cnt[tid]);
    }
}

// ---------------- fix kernel: SMEM-staged pair swaps + full recompute + aux ----------------
// exact logits replicate R1 fp32 order: even-k fmaf chain + odd-k fmaf chain, then add.
__global__ void __launch_bounds__(256, 1)
fix_kernel(const float* __restrict__ x, const float* __restrict__ w,
           float* __restrict__ out) {
    extern __shared__ float sf[];
    float* xs  = sf;                       // 128 x 129
    float* wsh = sf + 128 * 129;           // 64 x 129
    float* lgx = sf + 128 * 129 + 64 * 129; // 256

    const int tid = threadIdx.x;
    float* out_idx = out;
    float* out_wgt = out + (size_t)BT * TOPK;

    // ---- Part A: pairwise exact compare (128 pairs per block, smem-staged) ----
    const int npair = g_npair;
    for (int base = blockIdx.x * 128; base < npair; base += gridDim.x * 128) {
        const int tt   = tid & 127;
        const int side = tid >> 7;
        const int p    = base + tt;
        const bool act = (p < npair);
        const int pp   = act ? p : (npair - 1);
        const int info = g_pinfo[pp];
        const int e    = side ? ((info >> 9) & 63) : ((info >> 3) & 63);

        float accE = 0.f, accO = 0.f;
        for (int ch = 0; ch < 16; ch++) {
            __syncthreads();
            // stage x rows of the 128 tasks (coalesced within each row)
            for (int idx = tid; idx < 128 * 32; idx += 256) {
                int row = idx >> 5, q = idx & 31;
                int rp  = base + row;
                int trow = g_ptok[rp < npair ? rp : (npair - 1)];
                float4 v = *(const float4*)(x + (size_t)trow * CDIM + ch * 128 + q * 4);
                float* d = &xs[row * 129 + q * 4];
                d[0] = v.x; d[1] = v.y; d[2] = v.z; d[3] = v.w;
            }
            // stage all 64 expert rows
            for (int idx = tid; idx < 64 * 32; idx += 256) {
                int row = idx >> 5, q = idx & 31;
                float4 v = *(const float4*)(w + (size_t)row * CDIM + ch * 128 + q * 4);
                float* d = &wsh[row * 129 + q * 4];
                d[0] = v.x; d[1] = v.y; d[2] = v.z; d[3] = v.w;
            }
            __syncthreads();
            const float* xr = &xs[tt * 129];
            const float* wr = &wsh[e * 129];
#pragma unroll 8
            for (int kk = 0; kk < 128; kk += 2) {
                accE = fmaf(xr[kk],     wr[kk],     accE);
                accO = fmaf(xr[kk + 1], wr[kk + 1], accO);
            }
        }
        lgx[tid] = accE + accO;
        __syncthreads();

        if (act && side == 0) {
            float La = lgx[tid];
            float Lb = lgx[tid + 128];
            const int tok = g_ptok[pp];
            const int a  = info & 7;
            const int ia = (info >> 3) & 63;
            const int ib = (info >> 9) & 63;
            bool sw = (Lb > La);
            float2 pw = g_pw[pp];
            float fi = (float)(sw ? ib : ia), si = (float)(sw ? ia : ib);
            float fp = sw ? pw.y : pw.x,      sp = sw ? pw.x : pw.y;
            out_idx[(size_t)tok * TOPK + a] = fi;
            out_wgt[(size_t)tok * TOPK + a] = fp;
            if (a < 5) {
                out_idx[(size_t)tok * TOPK + a + 1] = si;
                out_wgt[(size_t)tok * TOPK + a + 1] = sp;
            }
        }
    }
    __syncthreads();

    // ---- Part B: full 64-expert exact recompute (rare) ----
    const int nfull = g_nfull;
    const int tg = tid >> 6;
    const int e  = tid & 63;
    float* lg = lgx;   // 4 x 64
    for (int base = blockIdx.x * 4; base < nfull; base += gridDim.x * 4) {
        const int fi = base + tg;
        const int tok = g_ffull[fi < nfull ? fi : (nfull - 1)];

        float accE = 0.f, accO = 0.f;
        for (int ch = 0; ch < 16; ch++) {
            __syncthreads();
            for (int i = tid; i < EXPN * 32; i += 256) {
                int row = i >> 5;
                int c4  = i & 31;
                float4 v = *(const float4*)(w + (size_t)row * CDIM + ch * 128 + c4 * 4);
                float* d = &wsh[row * 129 + c4 * 4];
                d[0] = v.x; d[1] = v.y; d[2] = v.z; d[3] = v.w;
            }
            __syncthreads();
            const float* xp = x + (size_t)tok * CDIM + ch * 128;
            const float* wr = &wsh[e * 129];
#pragma unroll 8
            for (int kk = 0; kk < 128; kk += 2) {
                float2 xv = *(const float2*)(xp + kk);
                accE = fmaf(xv.x, wr[kk],     accE);
                accO = fmaf(xv.y, wr[kk + 1], accO);
            }
        }
        lg[tg * 64 + e] = accE + accO;
        __syncthreads();

        if (tid < 4 && base + tid < nfull) {
            const int t2 = g_ffull[base + tid];
            const float* row = lg + tid * 64;
            float v0=-1e38f,v1=-1e38f,v2=-1e38f,v3=-1e38f,v4=-1e38f,v5=-1e38f;
            int   i0=0,i1=0,i2=0,i3=0,i4=0,i5=0;
            for (int k = 0; k < EXPN; k++) {
                float l = row[k];
                if (l > v5) {
                    v5 = l; i5 = k;
                    if (v5 > v4) { float t=v4; v4=v5; v5=t; int u=i4; i4=i5; i5=u; }
                    if (v4 > v3) { float t=v3; v3=v4; v4=t; int u=i3; i3=i4; i4=u; }
                    if (v3 > v2) { float t=v2; v2=v3; v3=t; int u=i2; i2=i3; i3=u; }
                    if (v2 > v1) { float t=v1; v1=v2; v2=t; int u=i1; i1=i2; i2=u; }
                    if (v1 > v0) { float t=v0; v0=v1; v1=t; int u=i0; i0=i1; i1=u; }
                }
            }
            float m = v0;
            float ssum = 0.f;
            for (int k = 0; k < EXPN; k++) ssum += expf(row[k] - m);
            float inv = 1.0f / ssum;
            const size_t g = (size_t)t2;
            out_idx[g * TOPK + 0] = (float)i0;
            out_idx[g * TOPK + 1] = (float)i1;
            out_idx[g * TOPK + 2] = (float)i2;
            out_idx[g * TOPK + 3] = (float)i3;
            out_idx[g * TOPK + 4] = (float)i4;
            out_idx[g * TOPK + 5] = (float)i5;
            out_wgt[g * TOPK + 0] = expf(v0 - m) * inv;
            out_wgt[g * TOPK + 1] = expf(v1 - m) * inv;
            out_wgt[g * TOPK + 2] = expf(v2 - m) * inv;
            out_wgt[g * TOPK + 3] = expf(v3 - m) * inv;
            out_wgt[g * TOPK + 4] = expf(v4 - m) * inv;
            out_wgt[g * TOPK + 5] = expf(v5 - m) * inv;
        }
        __syncthreads();
    }

    // ---- Part C: aux loss (block 0) ----
    if (blockIdx.x == 0) {
        float* red = xs;
        red[tid] = g_cnts[tid] * g_sums[tid];
        __syncthreads();
#pragma unroll
        for (int s = 128; s > 0; s >>= 1) {
            if (tid < s) red[tid] += red[tid + s];
            __syncthreads();
        }
        if (tid == 0) {
            const float scale = (float)(0.001 * 64.0 / ((double)4 * 4096.0 * 6.0 * 4096.0));
            out[(size_t)BT * 12] = red[0] * scale;
        }
    }
}

extern "C" void kernel_launch(void* const* d_in, const int* in_sizes, int n_in,
                              void* d_out, int out_size) {
    const float* x = (const float*)d_in[0];
    const float* w = (const float*)d_in[1];
    float* out = (float*)d_out;

    cudaFuncSetAttribute(gate_kernel, cudaFuncAttributeMaxDynamicSharedMemorySize, SMEM_BYTES);
    cudaFuncSetAttribute(fix_kernel, cudaFuncAttributeMaxDynamicSharedMemorySize, FIX_SMEM);

    prep_kernel<<<128, 256>>>(w);
    gate_kernel<<<BT / TOKB, NTHR, SMEM_BYTES>>>(x, out);
    fix_kernel<<<128, 256, FIX_SMEM>>>(x, w, out);
}

// round 8
// speedup vs baseline: 1.5132x; 1.5085x over previous
#include <cuda_runtime.h>
#include <cuda_bf16.h>
#include <cstdint>

#define NTHR 256
#define TOKB 128
#define EXPN 64
#define CDIM 2048
#define BT   16384
#define BDIM 4
#define TOPK 6
#define NKS  128                 // k-steps of 16
#define CH   4                   // k-steps per chunk
#define KSTEP_U32 1024           // u32 per k-step packed W (4 jp * 2 grp * 32 lanes * 4)
#define CHUNK_U32 (CH*KSTEP_U32) // 4096 u32 = 16 KB
#define LSTR 66
#define TAU  1.0e-4f
#define SMEM_BYTES (4*CHUNK_U32*4 + TOKB*LSTR*4)   // 65536 + 33792

__device__ float g_sums[BDIM * EXPN];
__device__ float g_cnts[BDIM * EXPN];
__device__ int   g_flagcnt;
__device__ int   g_flags[BT];
__device__ uint32_t wsg[NKS * KSTEP_U32];   // 512 KB packed 2-plane W fragments

static __device__ __forceinline__ void cp16(void* smem_ptr, const void* gptr) {
    unsigned saddr = (unsigned)__cvta_generic_to_shared(smem_ptr);
    asm volatile("cp.async.cg.shared.global [%0], [%1], 16;\n" :: "r"(saddr), "l"(gptr));
}
#define CP_COMMIT() asm volatile("cp.async.commit_group;\n" ::: "memory")

static __device__ __forceinline__ void mma16816(float* c, const uint32_t* a,
                                                uint32_t b0, uint32_t b1) {
    asm volatile("mma.sync.aligned.m16n8k16.row.col.f32.bf16.bf16.f32 "
        "{%0,%1,%2,%3}, {%4,%5,%6,%7}, {%8,%9}, {%0,%1,%2,%3};"
        : "+f"(c[0]), "+f"(c[1]), "+f"(c[2]), "+f"(c[3])
        : "r"(a[0]), "r"(a[1]), "r"(a[2]), "r"(a[3]), "r"(b0), "r"(b1));
}

// exact 2-way bf16 split of a float pair -> two bf16x2 words (lo=f0, hi=f1)
static __device__ __forceinline__ void split2(float f0, float f1,
                                              uint32_t& o0, uint32_t& o1) {
    __nv_bfloat162 b = __floats2bfloat162_rn(f0, f1);
    uint32_t u = *(uint32_t*)&b;
    o0 = u;
    float g0 = __int_as_float(u << 16);
    float g1 = __int_as_float(u & 0xffff0000u);
    __nv_bfloat162 c = __floats2bfloat162_rn(f0 - g0, f1 - g1);
    o1 = *(uint32_t*)&c;
}

// ---------------- W prep: 2-plane split, packed in B-fragment lane order ----------------
__global__ void prep_kernel(const float* __restrict__ w) {
    int id = blockIdx.x * 256 + threadIdx.x;   // 32768 = 128 ksteps * 8 ntiles * 32 lanes
    if (id < BDIM * EXPN) { g_sums[id] = 0.f; g_cnts[id] = 0.f; }
    if (id == 0) g_flagcnt = 0;
    int s = id >> 8;
    int j = (id >> 5) & 7;
    int l = id & 31;
    int n  = 8 * j + (l >> 2);
    int k0 = s * 16 + (l & 3) * 2;
    const float* wr = w + (size_t)n * CDIM + k0;
    float2 flo = *(const float2*)wr;        // b0 pair (k0, k0+1)
    float2 fhi = *(const float2*)(wr + 8);  // b1 pair (k0+8, k0+9)
    uint32_t A, B, C, D;
    split2(flo.x, flo.y, A, B);
    split2(fhi.x, fhi.y, C, D);
    uint32_t base = (uint32_t)(((s * 4 + (j >> 1)) * 2 + (j & 1)) * 128 + l * 4);
    *(uint4*)&wsg[base] = make_uint4(A, C, B, D);
}

// ---------------- main gate kernel ----------------
__global__ void __launch_bounds__(NTHR, 1)
gate_kernel(const float* __restrict__ x, float* __restrict__ out) {
    extern __shared__ char smem[];
    uint32_t* wbuf = (uint32_t*)smem;                 // 4 x 16KB chunk buffers
    float* lsm = (float*)(smem + 4 * CHUNK_U32 * 4);  // 128 x 66 logits
    __shared__ float s_sums[EXPN];
    __shared__ float s_cnt[EXPN];

    const int tid  = threadIdx.x;
    const int wid  = tid >> 5;
    const int lane = tid & 31;
    const int blk  = blockIdx.x;
    const int wg   = wid & 3;    // token group (32 tokens)
    const int kh   = wid >> 2;   // k-half

    if (tid < EXPN) { s_sums[tid] = 0.f; s_cnt[tid] = 0.f; }

    const int r  = lane >> 2;
    const int c0 = (lane & 3) * 2;
    const float* xr0 = x + ((size_t)blk * TOKB + wg * 32 + r) * CDIM + kh * 1024;
    const float* xr1 = xr0 + (size_t)16 * CDIM;

    float cacc[2][8][4];
#pragma unroll
    for (int m = 0; m < 2; m++)
#pragma unroll
        for (int j = 0; j < 8; j++)
#pragma unroll
            for (int q = 0; q < 4; q++) cacc[m][j][q] = 0.f;

    auto load2 = [&](int c) {
        int par = c & 1;
        const uint4* s0 = (const uint4*)(wsg + (size_t)c * CHUNK_U32);
        const uint4* s1 = (const uint4*)(wsg + (size_t)(16 + c) * CHUNK_U32);
        uint4* d0 = (uint4*)(wbuf + par * CHUNK_U32);
        uint4* d1 = (uint4*)(wbuf + (2 + par) * CHUNK_U32);
#pragma unroll
        for (int i = 0; i < 4; i++) cp16(d0 + tid + i * NTHR, s0 + tid + i * NTHR);
#pragma unroll
        for (int i = 0; i < 4; i++) cp16(d1 + tid + i * NTHR, s1 + tid + i * NTHR);
        CP_COMMIT();
    };

    load2(0);
    load2(1);

    for (int c = 0; c < 16; c++) {
        if (c + 1 < 16) asm volatile("cp.async.wait_group 1;\n" ::: "memory");
        else            asm volatile("cp.async.wait_group 0;\n" ::: "memory");
        __syncthreads();

        const uint32_t* wb = wbuf + (kh * 2 + (c & 1)) * CHUNK_U32;

#pragma unroll
        for (int kc = 0; kc < CH; kc++) {
            const int koff = (c * 4 + kc) * 16 + c0;
            uint32_t A0[2][4], A1[2][4];
#pragma unroll
            for (int m = 0; m < 2; m++) {
                const float* xp = (m == 0 ? xr0 : xr1) + koff;
                float2 l0 = *(const float2*)xp;
                float2 l1 = *(const float2*)(xp + 8 * CDIM);
                float2 h0 = *(const float2*)(xp + 8);
                float2 h1 = *(const float2*)(xp + 8 * CDIM + 8);
                split2(l0.x, l0.y, A0[m][0], A1[m][0]);
                split2(l1.x, l1.y, A0[m][1], A1[m][1]);
                split2(h0.x, h0.y, A0[m][2], A1[m][2]);
                split2(h1.x, h1.y, A0[m][3], A1[m][3]);
            }
            const uint4* wk = (const uint4*)(wb + kc * KSTEP_U32) + lane;
#pragma unroll
            for (int jp = 0; jp < 4; jp++) {
                uint4 G0 = wk[jp * 64];
                uint4 G1 = wk[jp * 64 + 32];
                float* e0 = cacc[0][2 * jp];
                float* o0 = cacc[0][2 * jp + 1];
                float* e1 = cacc[1][2 * jp];
                float* o1 = cacc[1][2 * jp + 1];
                // reuse distance 4; per-accumulator order identical to the
                // validated R5 realization (x0w0, x0w1, x1w0) => bit-identical logits
                mma16816(e0, A0[0], G0.x, G0.y);
                mma16816(o0, A0[0], G1.x, G1.y);
                mma16816(e1, A0[1], G0.x, G0.y);
                mma16816(o1, A0[1], G1.x, G1.y);
                mma16816(e0, A0[0], G0.z, G0.w);
                mma16816(o0, A0[0], G1.z, G1.w);
                mma16816(e1, A0[1], G0.z, G0.w);
                mma16816(o1, A0[1], G1.z, G1.w);
                mma16816(e0, A1[0], G0.x, G0.y);
                mma16816(o0, A1[0], G1.x, G1.y);
                mma16816(e1, A1[1], G0.x, G0.y);
                mma16816(o1, A1[1], G1.x, G1.y);
            }
        }
        __syncthreads();
        if (c + 2 < 16) load2(c + 2);
    }

    // ---- combine k-halves ----
    if (kh == 0) {
#pragma unroll
        for (int m = 0; m < 2; m++)
#pragma unroll
            for (int j = 0; j < 8; j++) {
                int row = wg * 32 + m * 16 + r;
                int nb = 8 * j + c0;
                *(float2*)&lsm[row * LSTR + nb]       = make_float2(cacc[m][j][0], cacc[m][j][1]);
                *(float2*)&lsm[(row + 8) * LSTR + nb] = make_float2(cacc[m][j][2], cacc[m][j][3]);
            }
    }
    __syncthreads();
    if (kh == 1) {
#pragma unroll
        for (int m = 0; m < 2; m++)
#pragma unroll
            for (int j = 0; j < 8; j++) {
                int row = wg * 32 + m * 16 + r;
                int nb = 8 * j + c0;
                float2 a = *(float2*)&lsm[row * LSTR + nb];
                float2 b = *(float2*)&lsm[(row + 8) * LSTR + nb];
                *(float2*)&lsm[row * LSTR + nb]       = make_float2(a.x + cacc[m][j][0], a.y + cacc[m][j][1]);
                *(float2*)&lsm[(row + 8) * LSTR + nb] = make_float2(b.x + cacc[m][j][2], b.y + cacc[m][j][3]);
            }
    }
    __syncthreads();

    // ---- per-token epilogue: top-7 tracking + flagging ----
    if (tid < TOKB) {
        float* row = lsm + tid * LSTR;

        float v0 = -1e38f, v1 = -1e38f, v2 = -1e38f, v3 = -1e38f, v4 = -1e38f, v5 = -1e38f, v6 = -1e38f;
        int   i0 = 0, i1 = 0, i2 = 0, i3 = 0, i4 = 0, i5 = 0;
        for (int e = 0; e < EXPN; e++) {
            float l = row[e];
            if (l > v6) {
                v6 = l;
                int ie = e;
                if (v6 > v5) { float t = v5; v5 = v6; v6 = t; int u = i5; i5 = ie; ie = u;
                if (v5 > v4) { t = v4; v4 = v5; v5 = t; u = i4; i4 = i5; i5 = u;
                if (v4 > v3) { t = v3; v3 = v4; v4 = t; u = i3; i3 = i4; i4 = u;
                if (v3 > v2) { t = v2; v2 = v3; v3 = t; u = i2; i2 = i3; i3 = u;
                if (v2 > v1) { t = v1; v1 = v2; v2 = t; u = i1; i1 = i2; i2 = u;
                if (v1 > v0) { t = v0; v0 = v1; v1 = t; u = i0; i0 = i1; i1 = u; } } } } } }
            }
        }

        float mg = v0 - v1;
        mg = fminf(mg, v1 - v2);
        mg = fminf(mg, v2 - v3);
        mg = fminf(mg, v3 - v4);
        mg = fminf(mg, v4 - v5);
        mg = fminf(mg, v5 - v6);
        const int tok = blk * TOKB + tid;
        if (mg < TAU) {
            int slot = atomicAdd(&g_flagcnt, 1);
            g_flags[slot] = tok;
        }

        float m = v0;
        float ssum = 0.f;
        for (int e = 0; e < EXPN; e++) {
            float p = expf(row[e] - m);
            ssum += p;
            row[e] = p;
        }
        float inv = 1.0f / ssum;

        const size_t g = (size_t)tok;
        float* out_idx = out;
        float* out_wgt = out + (size_t)BT * TOPK;

        out_idx[g * TOPK + 0] = (float)i0;
        out_idx[g * TOPK + 1] = (float)i1;
        out_idx[g * TOPK + 2] = (float)i2;
        out_idx[g * TOPK + 3] = (float)i3;
        out_idx[g * TOPK + 4] = (float)i4;
        out_idx[g * TOPK + 5] = (float)i5;

        out_wgt[g * TOPK + 0] = row[i0] * inv;
        out_wgt[g * TOPK + 1] = row[i1] * inv;
        out_wgt[g * TOPK + 2] = row[i2] * inv;
        out_wgt[g * TOPK + 3] = row[i3] * inv;
        out_wgt[g * TOPK + 4] = row[i4] * inv;
        out_wgt[g * TOPK + 5] = row[i5] * inv;

        for (int jj = 0; jj < EXPN; jj++) {
            int e = (tid + jj) & (EXPN - 1);
            atomicAdd(&s_sums[e], row[e] * inv);
        }
        atomicAdd(&s_cnt[i0], 1.0f);
        atomicAdd(&s_cnt[i1], 1.0f);
        atomicAdd(&s_cnt[i2], 1.0f);
        atomicAdd(&s_cnt[i3], 1.0f);
        atomicAdd(&s_cnt[i4], 1.0f);
        atomicAdd(&s_cnt[i5], 1.0f);
    }
    __syncthreads();

    if (tid < EXPN) {
        int b = blk >> 5;
        atomicAdd(&g_sums[b * EXPN + tid], s_sums[tid]);
        atomicAdd(&g_cnts[b * EXPN + tid], s_cnt[tid]);
    }
}

// ---------------- fixup: bit-exact replication of the R1 fp32 summation order ----------------
__global__ void __launch_bounds__(256, 1)
fixup_kernel(const float* __restrict__ x, const float* __restrict__ w,
             float* __restrict__ out) {
    __shared__ float ws[EXPN * 129];
    __shared__ float lg[4][EXPN];
    const int tid = threadIdx.x;
    const int tg  = tid >> 6;
    const int e   = tid & 63;
    const int nflag = g_flagcnt;

    for (int base = blockIdx.x * 4; base < nflag; base += gridDim.x * 4) {
        const int fi  = base + tg;
        const int tok = g_flags[fi < nflag ? fi : (nflag - 1)];

        float accE = 0.f, accO = 0.f;
        for (int ch = 0; ch < 16; ch++) {
            __syncthreads();
            for (int i = tid; i < EXPN * 32; i += 256) {
                int row = i >> 5;
                int c4  = i & 31;
                float4 v = *(const float4*)(w + (size_t)row * CDIM + ch * 128 + c4 * 4);
                float* d = &ws[row * 129 + c4 * 4];
                d[0] = v.x; d[1] = v.y; d[2] = v.z; d[3] = v.w;
            }
            __syncthreads();
            const float* xp = x + (size_t)tok * CDIM + ch * 128;
            const float* wr = &ws[e * 129];
#pragma unroll 8
            for (int kk = 0; kk < 128; kk += 2) {
                float2 xv = *(const float2*)(xp + kk);
                accE = fmaf(xv.x, wr[kk],     accE);
                accO = fmaf(xv.y, wr[kk + 1], accO);
            }
        }
        lg[tg][e] = accE + accO;
        __syncthreads();

        if (tid < 4 && base + tid < nflag) {
            const int t2 = g_flags[base + tid];
            const float* row = lg[tid];
            float v0 = -1e38f, v1 = -1e38f, v2 = -1e38f, v3 = -1e38f, v4 = -1e38f, v5 = -1e38f;
            int   i0 = 0, i1 = 0, i2 = 0, i3 = 0, i4 = 0, i5 = 0;
            for (int k = 0; k < EXPN; k++) {
                float l = row[k];
                if (l > v5) {
                    v5 = l; i5 = k;
                    if (v5 > v4) { float t = v4; v4 = v5; v5 = t; int u = i4; i4 = i5; i5 = u; }
                    if (v4 > v3) { float t = v3; v3 = v4; v4 = t; int u = i3; i3 = i4; i4 = u; }
                    if (v3 > v2) { float t = v2; v2 = v3; v3 = t; int u = i2; i2 = i3; i3 = u; }
                    if (v2 > v1) { float t = v1; v1 = v2; v2 = t; int u = i1; i1 = i2; i2 = u; }
                    if (v1 > v0) { float t = v0; v0 = v1; v1 = t; int u = i0; i0 = i1; i1 = u; }
                }
            }
            float m = v0;
            float ssum = 0.f;
            for (int k = 0; k < EXPN; k++) ssum += expf(row[k] - m);
            float inv = 1.0f / ssum;

            float* out_idx = out;
            float* out_wgt = out + (size_t)BT * TOPK;
            const size_t g = (size_t)t2;
            out_idx[g * TOPK + 0] = (float)i0;
            out_idx[g * TOPK + 1] = (float)i1;
            out_idx[g * TOPK + 2] = (float)i2;
            out_idx[g * TOPK + 3] = (float)i3;
            out_idx[g * TOPK + 4] = (float)i4;
            out_idx[g * TOPK + 5] = (float)i5;
            out_wgt[g * TOPK + 0] = expf(v0 - m) * inv;
            out_wgt[g * TOPK + 1] = expf(v1 - m) * inv;
            out_wgt[g * TOPK + 2] = expf(v2 - m) * inv;
            out_wgt[g * TOPK + 3] = expf(v3 - m) * inv;
            out_wgt[g * TOPK + 4] = expf(v4 - m) * inv;
            out_wgt[g * TOPK + 5] = expf(v5 - m) * inv;
        }
        __syncthreads();
    }
}

__global__ void aux_kernel(float* __restrict__ out) {
    __shared__ float red[256];
    int t = threadIdx.x;
    red[t] = g_cnts[t] * g_sums[t];
    __syncthreads();
#pragma unroll
    for (int s = 128; s > 0; s >>= 1) {
        if (t < s) red[t] += red[t + s];
        __syncthreads();
    }
    if (t == 0) {
        const float scale = (float)(0.001 * 64.0 / ((double)4 * 4096.0 * 6.0 * 4096.0));
        out[(size_t)BT * 12] = red[0] * scale;
    }
}

extern "C" void kernel_launch(void* const* d_in, const int* in_sizes, int n_in,
                              void* d_out, int out_size) {
    const float* x = (const float*)d_in[0];
    const float* w = (const float*)d_in[1];
    float* out = (float*)d_out;

    cudaFuncSetAttribute(gate_kernel, cudaFuncAttributeMaxDynamicSharedMemorySize, SMEM_BYTES);

    prep_kernel<<<128, 256>>>(w);
    gate_kernel<<<BT / TOKB, NTHR, SMEM_BYTES>>>(x, out);
    fixup_kernel<<<64, 256>>>(x, w, out);
    aux_kernel<<<1, 256>>>(out);
}